// round 1
// baseline (speedup 1.0000x reference)
#include <cuda_runtime.h>
#include <cstddef>

// Problem constants (fixed by setup_inputs)
#define BATCH   32
#define CHANS   256
#define HWSZ    3136          // 56*56
#define TP      64            // spatial positions per block tile (3136 = 49*64)
#define NSLOT   8             // channel slots per block
#define CPT     32            // channels per thread (NSLOT*CPT = 256)
#define STEPS   10
#define SCOPE   15
#define PAD     7

__global__ void __launch_bounds__(512, 1)
conv_rec_inhib_kernel(const float* __restrict__ x,
                      const float* __restrict__ w,
                      float* __restrict__ out)
{
    // Halo exchange buffers. Extra slab at each end stays zero forever and
    // provides the zero-padding at channel boundaries.
    //   s_bot[k][j][p]   = state channel (32k + j)        (written by slot k)
    //   s_top[k+1][j][p] = state channel (32k + 25 + j)   (written by slot k)
    // Reader slot k: below-halo = s_top[k] (k=0 -> zeros),
    //                above-halo = s_bot[k+1] (k=7 -> zeros).
    __shared__ float s_top[NSLOT + 1][PAD][TP];
    __shared__ float s_bot[NSLOT + 1][PAD][TP];

    const int t    = threadIdx.x;
    const int p    = t & (TP - 1);
    const int slot = t >> 6;
    const int tile = blockIdx.x;       // 0..48
    const int b    = blockIdx.y;       // 0..31

    // Zero the boundary slabs once (never overwritten afterwards).
    if (t < PAD * TP) {
        (&s_top[0][0][0])[t]              = 0.0f;
        (&s_bot[NSLOT][0][0])[t]          = 0.0f;
    }

    // 15 taps in registers (broadcast LDG)
    float wv[SCOPE];
#pragma unroll
    for (int k = 0; k < SCOPE; ++k) wv[k] = __ldg(&w[k]);

    // Load this thread's 32-channel column (coalesced across p)
    const size_t base_off = ((size_t)b * CHANS) * HWSZ + (size_t)tile * TP + p;
    const float* base = x + base_off;

    float xv[CPT], sv[CPT];
#pragma unroll
    for (int i = 0; i < CPT; ++i) {
        float v = base[(size_t)(slot * CPT + i) * HWSZ];
        xv[i] = v;
        sv[i] = v;   // initial state = x
    }

    float dly[PAD];  // rolling delay of pre-update values (channels i-7..i-1)
    float ha[PAD];   // above-halo (channels 32*slot+32 .. +38)

    for (int step = 0; step < STEPS; ++step) {
        __syncthreads();   // prior step's halo reads complete before overwrite
#pragma unroll
        for (int j = 0; j < PAD; ++j) {
            s_bot[slot][j][p]     = sv[j];
            s_top[slot + 1][j][p] = sv[25 + j];
        }
        __syncthreads();
#pragma unroll
        for (int j = 0; j < PAD; ++j) {
            dly[j] = s_top[slot][j][p];      // below-halo seeds the delay line
            ha[j]  = s_bot[slot + 1][j][p];  // above-halo
        }

#pragma unroll
        for (int i = 0; i < CPT; ++i) {
            float acc = xv[i];
#pragma unroll
            for (int o = -PAD; o <= PAD; ++o) {
                float v;
                if (o < 0)            v = dly[o + PAD];                    // pre-update values
                else if (o == 0)      v = sv[i];
                else if (i + o < CPT) v = sv[i + o];                       // not yet overwritten
                else                  v = ha[i + o - CPT];
                acc = fmaf(wv[o + PAD], v, acc);
            }
            // shift delay line (fully unrolled -> register renames)
#pragma unroll
            for (int j = 0; j < PAD - 1; ++j) dly[j] = dly[j + 1];
            dly[PAD - 1] = sv[i];
            sv[i] = acc;
        }
    }

    float* obase = out + base_off;
#pragma unroll
    for (int i = 0; i < CPT; ++i)
        obase[(size_t)(slot * CPT + i) * HWSZ] = sv[i];
}

extern "C" void kernel_launch(void* const* d_in, const int* in_sizes, int n_in,
                              void* d_out, int out_size)
{
    const float* acts = (const float*)d_in[0];
    const float* wrec = (const float*)d_in[1];
    float* out        = (float*)d_out;
    (void)in_sizes; (void)n_in; (void)out_size;

    dim3 grid(HWSZ / TP, BATCH);   // (49, 32)
    dim3 block(TP * NSLOT);        // 512
    conv_rec_inhib_kernel<<<grid, block>>>(acts, wrec, out);
}

// round 3
// speedup vs baseline: 1.4248x; 1.4248x over previous
#include <cuda_runtime.h>
#include <cstdint>
#include <cstddef>

#define CHANS 256
#define HWSZ  3136
#define BATCH 32
#define NPOS  (BATCH*HWSZ)        // 100352
#define STEPS 10
#define SCOPE 15
#define PADC  7

#define TILE_P 128
#define TILE_C 128
#define KC     32                 // K chunk per stage
#define NCHUNK (CHANS/KC)         // 8
#define XSTR   136                // padded row stride (floats): 136%32==8 -> conflict-free
#define WSTR   136
#define WT_FLOATS   (CHANS*WSTR)          // 34816
#define XBUF_FLOATS (KC*XSTR)             // 4352
#define SMEM_BYTES  ((WT_FLOATS + 2*XBUF_FLOATS)*4)   // 174080

// W_eff^T = (sum_{k=0..10} T^k)^T, tf32-pre-rounded: g_wt[cin][cout]
__device__ float g_wt[CHANS*CHANS];

// ---------------- helpers ----------------
__device__ __forceinline__ uint32_t smem_u32(const void* p){
    uint32_t a;
    asm("{ .reg .u64 t; cvta.to.shared.u64 t, %1; cvt.u32.u64 %0, t; }" : "=r"(a) : "l"(p));
    return a;
}
__device__ __forceinline__ uint32_t f2tf32(float f){
    uint32_t r; asm("cvt.rn.tf32.f32 %0, %1;" : "=r"(r) : "f"(f)); return r;
}
__device__ __forceinline__ void cp16(uint32_t dst, const void* src){
    asm volatile("cp.async.cg.shared.global [%0], [%1], 16;" :: "r"(dst), "l"(src));
}
__device__ __forceinline__ void cp_commit(){ asm volatile("cp.async.commit_group;" ::: "memory"); }
template<int N> __device__ __forceinline__ void cp_wait(){
    asm volatile("cp.async.wait_group %0;" :: "n"(N) : "memory");
}
__device__ __forceinline__ void mma8(float* d, const uint32_t* a, uint32_t b0, uint32_t b1){
    asm volatile("mma.sync.aligned.m16n8k8.row.col.f32.tf32.tf32.f32 "
        "{%0,%1,%2,%3}, {%4,%5,%6,%7}, {%8,%9}, {%0,%1,%2,%3};"
        : "+f"(d[0]), "+f"(d[1]), "+f"(d[2]), "+f"(d[3])
        : "r"(a[0]), "r"(a[1]), "r"(a[2]), "r"(a[3]), "r"(b0), "r"(b1));
}

// ---------------- Kernel 1: build W_eff^T ----------------
// Block j computes column j of S = sum_{k=0..STEPS} T^k via the matrix recurrence
// S_{s+1} = I + T*S_s (exact, includes zero-pad boundary effects).
// Thread i holds S[i][j]; writes g_wt[j*CHANS + i] (row j = cin, coalesced).
__global__ void build_weff_kernel(const float* __restrict__ w){
    __shared__ float sv[CHANS + 2*PADC];
    const int i = threadIdx.x, j = blockIdx.x;
    if (i < PADC){ sv[i] = 0.f; sv[CHANS + PADC + i] = 0.f; }
    float wv[SCOPE];
#pragma unroll
    for (int k = 0; k < SCOPE; ++k) wv[k] = w[k];
    float v = (i == j) ? 1.f : 0.f;
    for (int s = 0; s < STEPS; ++s){
        __syncthreads();
        sv[PADC + i] = v;
        __syncthreads();
        float acc = (i == j) ? 1.f : 0.f;
#pragma unroll
        for (int k = 0; k < SCOPE; ++k) acc = fmaf(wv[k], sv[i + k], acc);
        v = acc;
    }
    g_wt[j * CHANS + i] = __uint_as_float(f2tf32(v));
}

// ---------------- Kernel 2: out = W_eff * X via tf32 mma.sync ----------------
// D tile 128pos(M) x 128cout(N). A = X (pos x cin), B = Wt (cin x cout).
// 8 warps: wp = wid>>1 (pos quarter), wc = wid&1 (cout half-of-half).
// Warp tile: 32 pos (2 M-tiles) x 64 cout (8 N-tiles), acc = 64 regs.
__global__ void __launch_bounds__(256, 1)
gemm_kernel(const float* __restrict__ x, float* __restrict__ out){
    extern __shared__ float sm[];
    float* wt  = sm;               // [256][WSTR]
    float* xb0 = sm + WT_FLOATS;   // 2 x [KC][XSTR]

    const int tid  = threadIdx.x;
    const int lane = tid & 31;
    const int wid  = tid >> 5;
    const int g = lane >> 2, q = lane & 3;
    const int wp = wid >> 1, wc = wid & 1;
    const int chalf = blockIdx.x;      // 0..1 (adjacent bids share X -> L2 reuse)
    const int tile  = blockIdx.y;      // 0..783

    // stage Wt half: g_wt[k][chalf*128 + c] -> wt[k][c], 16B cp.async
    {
        const float* wsrc = g_wt + chalf * TILE_C;
#pragma unroll
        for (int i = 0; i < 32; ++i){
            int id = tid + i * 256;
            int k = id >> 5, j4 = (id & 31) << 2;
            cp16(smem_u32(wt + k * WSTR + j4), wsrc + (size_t)k * CHANS + j4);
        }
    }
    // X chunk stage: rows = cin (KC), cols = 128 global-pos (handles batch crossings)
    auto stage_x = [&](int kc, float* buf){
#pragma unroll
        for (int i = 0; i < 4; ++i){
            int id = tid + i * 256;
            int kr = id >> 5, j4 = (id & 31) << 2;
            int n4 = tile * TILE_P + j4;
            int b  = n4 / HWSZ;
            int p  = n4 - b * HWSZ;    // 3136%4==0 -> float4 never straddles batches
            const float* src = x + ((size_t)b * CHANS + (size_t)(kc * KC + kr)) * HWSZ + p;
            cp16(smem_u32(buf + kr * XSTR + j4), src);
        }
    };
    stage_x(0, xb0);               cp_commit();   // group: Wt + chunk0
    stage_x(1, xb0 + XBUF_FLOATS); cp_commit();   // group: chunk1

    float acc[2][8][4];
#pragma unroll
    for (int mt = 0; mt < 2; ++mt)
#pragma unroll
        for (int nt = 0; nt < 8; ++nt)
#pragma unroll
            for (int r = 0; r < 4; ++r) acc[mt][nt][r] = 0.f;

    for (int c = 0; c < NCHUNK; ++c){
        if (c < NCHUNK - 1) cp_wait<1>(); else cp_wait<0>();
        __syncthreads();
        const float* fb = xb0 + (c & 1) * XBUF_FLOATS;
#pragma unroll
        for (int ks = 0; ks < 4; ++ks){
            // A fragments (pos x k8) from X chunk; bank pattern 8q+g = permutation
            const float* xr0 = fb + (ks * 8 + q) * XSTR + wp * 32;
            const float* xr1 = xr0 + 4 * XSTR;
            uint32_t a[2][4];
#pragma unroll
            for (int mt = 0; mt < 2; ++mt){
                a[mt][0] = f2tf32(xr0[mt * 16 + g]);
                a[mt][1] = f2tf32(xr0[mt * 16 + g + 8]);
                a[mt][2] = f2tf32(xr1[mt * 16 + g]);
                a[mt][3] = f2tf32(xr1[mt * 16 + g + 8]);
            }
            // B fragments (k8 x cout8) from Wt (already tf32-rounded)
            const float* wr0 = wt + (size_t)(c * KC + ks * 8 + q) * WSTR + wc * 64 + g;
            const float* wr1 = wr0 + 4 * WSTR;
#pragma unroll
            for (int nt = 0; nt < 8; ++nt){
                uint32_t b0 = __float_as_uint(wr0[nt * 8]);
                uint32_t b1 = __float_as_uint(wr1[nt * 8]);
                mma8(acc[0][nt], a[0], b0, b1);
                mma8(acc[1][nt], a[1], b0, b1);
            }
        }
        if (c + 2 < NCHUNK){
            __syncthreads();                    // everyone done reading this buffer
            stage_x(c + 2, xb0 + (c & 1) * XBUF_FLOATS);
            cp_commit();
        }
    }

    // epilogue: D frag (row g|g+8, cols 2q,2q+1) -> out[cout][b,p]
#pragma unroll
    for (int mt = 0; mt < 2; ++mt){
#pragma unroll
        for (int rs = 0; rs < 2; ++rs){
            int pos = tile * TILE_P + wp * 32 + mt * 16 + g + rs * 8;
            int b = pos / HWSZ, p = pos - b * HWSZ;
            float* ob = out + ((size_t)b * CHANS + (size_t)(chalf * TILE_C + wc * 64 + 2 * q)) * HWSZ + p;
#pragma unroll
            for (int nt = 0; nt < 8; ++nt){
                ob[(size_t)(nt * 8) * HWSZ]     = acc[mt][nt][rs * 2 + 0];
                ob[(size_t)(nt * 8 + 1) * HWSZ] = acc[mt][nt][rs * 2 + 1];
            }
        }
    }
}

// ---------------- launch ----------------
extern "C" void kernel_launch(void* const* d_in, const int* in_sizes, int n_in,
                              void* d_out, int out_size)
{
    const float* acts = (const float*)d_in[0];
    const float* wrec = (const float*)d_in[1];
    float* out        = (float*)d_out;
    (void)in_sizes; (void)n_in; (void)out_size;

    cudaFuncSetAttribute(gemm_kernel, cudaFuncAttributeMaxDynamicSharedMemorySize, SMEM_BYTES);

    build_weff_kernel<<<CHANS, CHANS>>>(wrec);
    gemm_kernel<<<dim3(2, NPOS / TILE_P), 256, SMEM_BYTES>>>(acts, out);
}

// round 4
// speedup vs baseline: 1.6980x; 1.1918x over previous
#include <cuda_runtime.h>
#include <cstdint>
#include <cstddef>

#define CHANS 256
#define HWSZ  3136
#define BATCH 32
#define NPOS  (BATCH*HWSZ)        // 100352
#define STEPS 10
#define SCOPE 15
#define PADC  7

#define TILE_P 128
#define TILE_C 128
#define KC     32                 // K chunk per stage
#define NCHUNK (CHANS/KC)         // 8
#define RSTR   136                // padded row stride: %32==8 -> conflict-free frag loads
#define BUF_FLOATS (KC*RSTR)      // 4352
#define SMEM_BYTES (4*BUF_FLOATS*4)   // 2x X buf + 2x W buf = 69632 B -> 2 CTAs/SM

// W_eff^T = (sum_{k=0..10} T^k)^T, tf32-pre-rounded: g_wt[cin][cout]
__device__ float g_wt[CHANS*CHANS];

// ---------------- helpers ----------------
__device__ __forceinline__ uint32_t smem_u32(const void* p){
    uint32_t a;
    asm("{ .reg .u64 t; cvta.to.shared.u64 t, %1; cvt.u32.u64 %0, t; }" : "=r"(a) : "l"(p));
    return a;
}
__device__ __forceinline__ uint32_t f2tf32(float f){
    uint32_t r; asm("cvt.rn.tf32.f32 %0, %1;" : "=r"(r) : "f"(f)); return r;
}
__device__ __forceinline__ void cp16(uint32_t dst, const void* src){
    asm volatile("cp.async.cg.shared.global [%0], [%1], 16;" :: "r"(dst), "l"(src));
}
__device__ __forceinline__ void cp_commit(){ asm volatile("cp.async.commit_group;" ::: "memory"); }
template<int N> __device__ __forceinline__ void cp_wait(){
    asm volatile("cp.async.wait_group %0;" :: "n"(N) : "memory");
}
__device__ __forceinline__ void mma8(float* d, const uint32_t* a, uint32_t b0, uint32_t b1){
    asm volatile("mma.sync.aligned.m16n8k8.row.col.f32.tf32.tf32.f32 "
        "{%0,%1,%2,%3}, {%4,%5,%6,%7}, {%8,%9}, {%0,%1,%2,%3};"
        : "+f"(d[0]), "+f"(d[1]), "+f"(d[2]), "+f"(d[3])
        : "r"(a[0]), "r"(a[1]), "r"(a[2]), "r"(a[3]), "r"(b0), "r"(b1));
}

// ---------------- Kernel 1: build W_eff^T ----------------
// Block j computes column j of S = sum_{k=0..STEPS} T^k via S_{s+1} = I + T*S_s
// (exact, includes zero-pad boundary effects). Writes transposed, tf32-rounded.
__global__ void build_weff_kernel(const float* __restrict__ w){
    __shared__ float sv[CHANS + 2*PADC];
    const int i = threadIdx.x, j = blockIdx.x;
    if (i < PADC){ sv[i] = 0.f; sv[CHANS + PADC + i] = 0.f; }
    float wv[SCOPE];
#pragma unroll
    for (int k = 0; k < SCOPE; ++k) wv[k] = w[k];
    float v = (i == j) ? 1.f : 0.f;
    for (int s = 0; s < STEPS; ++s){
        __syncthreads();
        sv[PADC + i] = v;
        __syncthreads();
        float acc = (i == j) ? 1.f : 0.f;
#pragma unroll
        for (int k = 0; k < SCOPE; ++k) acc = fmaf(wv[k], sv[i + k], acc);
        v = acc;
    }
    g_wt[j * CHANS + i] = __uint_as_float(f2tf32(v));
}

// ---------------- Kernel 2: out = W_eff * X via tf32 mma.sync ----------------
// D tile 128pos(M) x 128cout(N), K=256 in 8 double-buffered chunks of 32
// (both X and W streamed; W_eff stays hot in L2). 8 warps: wp=wid>>1 (pos
// quarter), wc=wid&1 (cout half). Warp tile 32pos x 64cout, 64 acc regs.
// 2 CTAs/SM (smem 70KB, regs<=128).
__global__ void __launch_bounds__(256, 2)
gemm_kernel(const float* __restrict__ x, float* __restrict__ out){
    extern __shared__ float sm[];
    float* xbuf = sm;                   // 2 x [KC][RSTR]
    float* wbuf = sm + 2*BUF_FLOATS;    // 2 x [KC][RSTR]

    const int tid  = threadIdx.x;
    const int lane = tid & 31;
    const int wid  = tid >> 5;
    const int g = lane >> 2, q = lane & 3;
    const int wp = wid >> 1, wc = wid & 1;
    const int chalf = blockIdx.x;      // 0..1 (adjacent bids share X in L2)
    const int tile  = blockIdx.y;      // 0..783

    // X chunk: rows = cin (KC), cols = 128 global-pos (3136%4==0: no straddle)
    auto stage_x = [&](int kc, float* buf){
#pragma unroll
        for (int i = 0; i < 4; ++i){
            int id = tid + i * 256;
            int kr = id >> 5, j4 = (id & 31) << 2;
            int n4 = tile * TILE_P + j4;
            int b  = n4 / HWSZ;
            int p  = n4 - b * HWSZ;
            const float* src = x + ((size_t)b * CHANS + (size_t)(kc * KC + kr)) * HWSZ + p;
            cp16(smem_u32(buf + kr * RSTR + j4), src);
        }
    };
    // W chunk: rows = cin (KC), cols = 128 couts of this half (L2-resident)
    auto stage_w = [&](int kc, float* buf){
        const float* wsrc = g_wt + (size_t)(kc * KC) * CHANS + chalf * TILE_C;
#pragma unroll
        for (int i = 0; i < 4; ++i){
            int id = tid + i * 256;
            int kr = id >> 5, j4 = (id & 31) << 2;
            cp16(smem_u32(buf + kr * RSTR + j4), wsrc + (size_t)kr * CHANS + j4);
        }
    };

    stage_x(0, xbuf);              stage_w(0, wbuf);              cp_commit();
    stage_x(1, xbuf + BUF_FLOATS); stage_w(1, wbuf + BUF_FLOATS); cp_commit();

    float acc[2][8][4];
#pragma unroll
    for (int mt = 0; mt < 2; ++mt)
#pragma unroll
        for (int nt = 0; nt < 8; ++nt)
#pragma unroll
            for (int r = 0; r < 4; ++r) acc[mt][nt][r] = 0.f;

    for (int c = 0; c < NCHUNK; ++c){
        if (c < NCHUNK - 1) cp_wait<1>(); else cp_wait<0>();
        __syncthreads();
        const float* xb = xbuf + (c & 1) * BUF_FLOATS;
        const float* wb = wbuf + (c & 1) * BUF_FLOATS;
#pragma unroll
        for (int ks = 0; ks < 4; ++ks){
            // A fragments (pos x k8); bank pattern 8q+g is a permutation
            const float* xr0 = xb + (ks * 8 + q) * RSTR + wp * 32;
            const float* xr1 = xr0 + 4 * RSTR;
            uint32_t a[2][4];
#pragma unroll
            for (int mt = 0; mt < 2; ++mt){
                a[mt][0] = f2tf32(xr0[mt * 16 + g]);
                a[mt][1] = f2tf32(xr0[mt * 16 + g + 8]);
                a[mt][2] = f2tf32(xr1[mt * 16 + g]);
                a[mt][3] = f2tf32(xr1[mt * 16 + g + 8]);
            }
            // B fragments (k8 x cout8) — already tf32-rounded
            const float* wr0 = wb + (ks * 8 + q) * RSTR + wc * 64 + g;
            const float* wr1 = wr0 + 4 * RSTR;
#pragma unroll
            for (int nt = 0; nt < 8; ++nt){
                uint32_t b0 = __float_as_uint(wr0[nt * 8]);
                uint32_t b1 = __float_as_uint(wr1[nt * 8]);
                mma8(acc[0][nt], a[0], b0, b1);
                mma8(acc[1][nt], a[1], b0, b1);
            }
        }
        if (c + 2 < NCHUNK){
            __syncthreads();                 // all reads of buffer (c&1) done
            stage_x(c + 2, xbuf + (c & 1) * BUF_FLOATS);
            stage_w(c + 2, wbuf + (c & 1) * BUF_FLOATS);
            cp_commit();
        }
    }

    // epilogue: frag (rows g|g+8, cols 2q,2q+1) -> out[cout][b,p]
    // lanes with equal q cover 8 contiguous pos -> full 32B sectors
#pragma unroll
    for (int mt = 0; mt < 2; ++mt){
#pragma unroll
        for (int rs = 0; rs < 2; ++rs){
            int pos = tile * TILE_P + wp * 32 + mt * 16 + g + rs * 8;
            int b = pos / HWSZ, p = pos - b * HWSZ;
            float* ob = out + ((size_t)b * CHANS + (size_t)(chalf * TILE_C + wc * 64 + 2 * q)) * HWSZ + p;
#pragma unroll
            for (int nt = 0; nt < 8; ++nt){
                ob[(size_t)(nt * 8) * HWSZ]     = acc[mt][nt][rs * 2 + 0];
                ob[(size_t)(nt * 8 + 1) * HWSZ] = acc[mt][nt][rs * 2 + 1];
            }
        }
    }
}

// ---------------- launch ----------------
extern "C" void kernel_launch(void* const* d_in, const int* in_sizes, int n_in,
                              void* d_out, int out_size)
{
    const float* acts = (const float*)d_in[0];
    const float* wrec = (const float*)d_in[1];
    float* out        = (float*)d_out;
    (void)in_sizes; (void)n_in; (void)out_size;

    cudaFuncSetAttribute(gemm_kernel, cudaFuncAttributeMaxDynamicSharedMemorySize, SMEM_BYTES);

    build_weff_kernel<<<CHANS, CHANS>>>(wrec);
    gemm_kernel<<<dim3(2, NPOS / TILE_P), 256, SMEM_BYTES>>>(acts, out);
}

// round 5
// speedup vs baseline: 2.1257x; 1.2519x over previous
#include <cuda_runtime.h>
#include <cuda_fp16.h>
#include <cstdint>
#include <cstddef>

#define CHANS 256
#define HWSZ  3136
#define BATCH 32
#define NPOS  (BATCH*HWSZ)        // 100352
#define STEPS 10
#define SCOPE 15
#define PADC  7

#define TILE_P 128
#define TILE_C 128
#define KC     32                 // K (cin) per stage
#define NCHUNK (CHANS/KC)         // 8
#define XSTR   132                // fp32 X row stride: %32==4 -> A-frag perm (8q+g)
#define WSTR   136                // uint32 W row stride: %32==8 -> B-frag perm
#define XBUF   (KC*XSTR)          // 4224 floats
#define WBUF   ((KC/2)*WSTR)      // 2176 uint32
#define SMEM_BYTES ((2*XBUF + 2*WBUF)*4)   // 51200 B -> 2 CTAs/SM

// W_eff = sum_{k=0..10} T^k, fp16: g_wh[cin][cout]
__device__ __half g_wh[CHANS*CHANS];

// ---------------- helpers ----------------
__device__ __forceinline__ uint32_t smem_u32(const void* p){
    uint32_t a;
    asm("{ .reg .u64 t; cvta.to.shared.u64 t, %1; cvt.u32.u64 %0, t; }" : "=r"(a) : "l"(p));
    return a;
}
__device__ __forceinline__ void cp16(uint32_t dst, const void* src){
    asm volatile("cp.async.cg.shared.global [%0], [%1], 16;" :: "r"(dst), "l"(src));
}
__device__ __forceinline__ void cp_commit(){ asm volatile("cp.async.commit_group;" ::: "memory"); }
template<int N> __device__ __forceinline__ void cp_wait(){
    asm volatile("cp.async.wait_group %0;" :: "n"(N) : "memory");
}
__device__ __forceinline__ uint32_t pkh2(float hi, float lo){
    uint32_t r; asm("cvt.rn.f16x2.f32 %0, %1, %2;" : "=r"(r) : "f"(hi), "f"(lo)); return r;
}
__device__ __forceinline__ uint32_t prmt(uint32_t a, uint32_t b, uint32_t sel){
    uint32_t r; asm("prmt.b32 %0, %1, %2, %3;" : "=r"(r) : "r"(a), "r"(b), "r"(sel)); return r;
}
__device__ __forceinline__ void mma16(float* d, const uint32_t* a, uint32_t b0, uint32_t b1){
    asm volatile("mma.sync.aligned.m16n8k16.row.col.f32.f16.f16.f32 "
        "{%0,%1,%2,%3}, {%4,%5,%6,%7}, {%8,%9}, {%0,%1,%2,%3};"
        : "+f"(d[0]), "+f"(d[1]), "+f"(d[2]), "+f"(d[3])
        : "r"(a[0]), "r"(a[1]), "r"(a[2]), "r"(a[3]), "r"(b0), "r"(b1));
}

// ---------------- Kernel 1: build W_eff (fp16) ----------------
// Block j: column j of S = sum_{k=0..STEPS} T^k via S_{s+1} = I + T*S_s (exact,
// includes zero-pad boundaries). Thread i holds S[i][j] = W[cout=i][cin=j];
// writes g_wh[cin=j][cout=i] (coalesced).
__global__ void build_weff_kernel(const float* __restrict__ w){
    __shared__ float sv[CHANS + 2*PADC];
    const int i = threadIdx.x, j = blockIdx.x;
    if (i < PADC){ sv[i] = 0.f; sv[CHANS + PADC + i] = 0.f; }
    float wv[SCOPE];
#pragma unroll
    for (int k = 0; k < SCOPE; ++k) wv[k] = w[k];
    float v = (i == j) ? 1.f : 0.f;
    for (int s = 0; s < STEPS; ++s){
        __syncthreads();
        sv[PADC + i] = v;
        __syncthreads();
        float acc = (i == j) ? 1.f : 0.f;
#pragma unroll
        for (int k = 0; k < SCOPE; ++k) acc = fmaf(wv[k], sv[i + k], acc);
        v = acc;
    }
    g_wh[j * CHANS + i] = __float2half_rn(v);
}

// ---------------- Kernel 2: out = W_eff * X via fp16 mma.sync ----------------
// D tile 128pos x 128cout, K=256 in 8 double-buffered chunks of 32.
// A (X) staged fp32 via cp.async, converted to fp16 at fragment load.
// B (W) staged k-paired fp16 {W(2k,n),W(2k+1,n)} per uint32 via LDG+PRMT.
// 8 warps: wp=wid>>1 pos quarter, wc=wid&1 cout half. Warp tile 32x64.
__global__ void __launch_bounds__(256, 2)
gemm_kernel(const float* __restrict__ x, float* __restrict__ out){
    extern __shared__ float sm[];
    float*    xbuf = sm;                               // 2 x [KC][XSTR] fp32
    uint32_t* wbuf = (uint32_t*)(sm + 2*XBUF);         // 2 x [KC/2][WSTR] h2

    const int tid  = threadIdx.x;
    const int lane = tid & 31;
    const int wid  = tid >> 5;
    const int g = lane >> 2, q = lane & 3;
    const int wp = wid >> 1, wc = wid & 1;
    const int chalf = blockIdx.x;      // 0..1
    const int tile  = blockIdx.y;      // 0..783

    // X chunk: rows = cin (KC), 128 pos (3136%4==0: float4 never straddles b)
    auto stage_x = [&](int kc, float* buf){
#pragma unroll
        for (int i = 0; i < 4; ++i){
            int id = tid + i * 256;
            int kr = id >> 5, j4 = (id & 31) << 2;
            int n4 = tile * TILE_P + j4;
            int b  = n4 / HWSZ;
            int p  = n4 - b * HWSZ;
            const float* src = x + ((size_t)b * CHANS + (size_t)(kc * KC + kr)) * HWSZ + p;
            cp16(smem_u32(buf + kr * XSTR + j4), src);
        }
    };
    // W chunk: k-paired interleave, rows k2 (KC/2), 128 couts (L2-resident)
    auto stage_w = [&](int kc, uint32_t* buf){
#pragma unroll
        for (int i = 0; i < 4; ++i){
            int id  = tid + i * 256;            // 0..1023
            int k2l = id >> 6;                  // 0..15
            int n2  = (id & 63) << 1;           // even cout pair
            const __half* r0 = g_wh + (size_t)(kc * KC + 2 * k2l) * CHANS + chalf * TILE_C + n2;
            uint32_t a = *(const uint32_t*)r0;           // {W(2k,n), W(2k,n+1)}
            uint32_t b = *(const uint32_t*)(r0 + CHANS); // {W(2k+1,n), W(2k+1,n+1)}
            uint32_t lo = prmt(a, b, 0x5410);   // {W(2k,n),   W(2k+1,n)}
            uint32_t hi = prmt(a, b, 0x7632);   // {W(2k,n+1), W(2k+1,n+1)}
            *(uint2*)(buf + k2l * WSTR + n2) = make_uint2(lo, hi);
        }
    };

    stage_w(0, wbuf);        stage_x(0, xbuf);        cp_commit();
    stage_w(1, wbuf + WBUF); stage_x(1, xbuf + XBUF); cp_commit();

    float acc[2][8][4];
#pragma unroll
    for (int mt = 0; mt < 2; ++mt)
#pragma unroll
        for (int nt = 0; nt < 8; ++nt)
#pragma unroll
            for (int r = 0; r < 4; ++r) acc[mt][nt][r] = 0.f;

    for (int c = 0; c < NCHUNK; ++c){
        if (c < NCHUNK - 1) cp_wait<1>(); else cp_wait<0>();
        __syncthreads();
        const float*    xb = xbuf + (c & 1) * XBUF;
        const uint32_t* wb = wbuf + (c & 1) * WBUF;
#pragma unroll
        for (int ks = 0; ks < 2; ++ks){
            // A fragments: rows k = ks*16 + {2q,2q+1,2q+8,2q+9}; conflict-free
            const float* xk = xb + (ks * 16 + 2 * q) * XSTR + wp * 32;
            uint32_t a[2][4];
#pragma unroll
            for (int mt = 0; mt < 2; ++mt){
                int p0 = mt * 16 + g;
                a[mt][0] = pkh2(xk[XSTR + p0],     xk[p0]);
                a[mt][1] = pkh2(xk[XSTR + p0 + 8], xk[p0 + 8]);
                a[mt][2] = pkh2(xk[9*XSTR + p0],     xk[8*XSTR + p0]);
                a[mt][3] = pkh2(xk[9*XSTR + p0 + 8], xk[8*XSTR + p0 + 8]);
            }
            // B fragments: k-paired uint32, one LDS.32 each
            const uint32_t* wk = wb + (ks * 8 + q) * WSTR + wc * 64 + g;
#pragma unroll
            for (int nt = 0; nt < 8; ++nt){
                uint32_t b0 = wk[nt * 8];
                uint32_t b1 = wk[4 * WSTR + nt * 8];
                mma16(acc[0][nt], a[0], b0, b1);
                mma16(acc[1][nt], a[1], b0, b1);
            }
        }
        if (c + 2 < NCHUNK){
            __syncthreads();                 // all reads of buffer (c&1) done
            stage_w(c + 2, wbuf + (c & 1) * WBUF);
            stage_x(c + 2, xbuf + (c & 1) * XBUF);
            cp_commit();
        }
    }

    // epilogue: frag rows g|g+8, cols 2q,2q+1 -> out[cout][b,p]
#pragma unroll
    for (int mt = 0; mt < 2; ++mt){
#pragma unroll
        for (int rs = 0; rs < 2; ++rs){
            int pos = tile * TILE_P + wp * 32 + mt * 16 + g + rs * 8;
            int b = pos / HWSZ, p = pos - b * HWSZ;
            float* ob = out + ((size_t)b * CHANS + (size_t)(chalf * TILE_C + wc * 64 + 2 * q)) * HWSZ + p;
#pragma unroll
            for (int nt = 0; nt < 8; ++nt){
                ob[(size_t)(nt * 8) * HWSZ]     = acc[mt][nt][rs * 2 + 0];
                ob[(size_t)(nt * 8 + 1) * HWSZ] = acc[mt][nt][rs * 2 + 1];
            }
        }
    }
}

// ---------------- launch ----------------
extern "C" void kernel_launch(void* const* d_in, const int* in_sizes, int n_in,
                              void* d_out, int out_size)
{
    const float* acts = (const float*)d_in[0];
    const float* wrec = (const float*)d_in[1];
    float* out        = (float*)d_out;
    (void)in_sizes; (void)n_in; (void)out_size;

    cudaFuncSetAttribute(gemm_kernel, cudaFuncAttributeMaxDynamicSharedMemorySize, SMEM_BYTES);

    build_weff_kernel<<<CHANS, CHANS>>>(wrec);
    gemm_kernel<<<dim3(2, NPOS / TILE_P), 256, SMEM_BYTES>>>(acts, out);
}

// round 6
// speedup vs baseline: 2.1716x; 1.0216x over previous
#include <cuda_runtime.h>
#include <cuda_fp16.h>
#include <cstdint>
#include <cstddef>

#define CHANS 256
#define HWSZ  3136
#define BATCH 32
#define NPOS  (BATCH*HWSZ)        // 100352
#define STEPS 10
#define SCOPE 15
#define PADC  7

#define TILE_P 128
#define TILE_C 128
#define KC     32                 // cin per chunk
#define NCHUNK (CHANS/KC)         // 8
#define XSTR   136                // u32 row stride: %32==8 -> 8q+g bank permutation
#define WSTR   136
#define XBUF   (16*XSTR)          // 2176 u32 per buffer (16 k2-rows x 128 pos)
#define WBUF   (16*WSTR)
#define SMEM_BYTES ((2*XBUF + 2*WBUF)*4)   // 34816 B -> 2 CTAs/SM

// W_eff = sum_{k=0..10} T^k, fp16: g_wh[cin][cout]
__device__ __half g_wh[CHANS*CHANS];

// ---------------- helpers ----------------
__device__ __forceinline__ uint32_t pkh2(float hi, float lo){
    uint32_t r; asm("cvt.rn.f16x2.f32 %0, %1, %2;" : "=r"(r) : "f"(hi), "f"(lo)); return r;
}
__device__ __forceinline__ uint32_t prmt(uint32_t a, uint32_t b, uint32_t sel){
    uint32_t r; asm("prmt.b32 %0, %1, %2, %3;" : "=r"(r) : "r"(a), "r"(b), "r"(sel)); return r;
}
__device__ __forceinline__ void mma16(float* d, const uint32_t* a, uint32_t b0, uint32_t b1){
    asm volatile("mma.sync.aligned.m16n8k16.row.col.f32.f16.f16.f32 "
        "{%0,%1,%2,%3}, {%4,%5,%6,%7}, {%8,%9}, {%0,%1,%2,%3};"
        : "+f"(d[0]), "+f"(d[1]), "+f"(d[2]), "+f"(d[3])
        : "r"(a[0]), "r"(a[1]), "r"(a[2]), "r"(a[3]), "r"(b0), "r"(b1));
}

// ---------------- Kernel 1: build W_eff (fp16) ----------------
// Block j: column j of S = sum_{k=0..STEPS} T^k via S_{s+1} = I + T*S_s (exact,
// includes zero-pad boundaries). Thread i holds S[i][j] = W[cout=i][cin=j];
// writes g_wh[cin=j][cout=i] (coalesced).
__global__ void build_weff_kernel(const float* __restrict__ w){
    __shared__ float sv[CHANS + 2*PADC];
    const int i = threadIdx.x, j = blockIdx.x;
    if (i < PADC){ sv[i] = 0.f; sv[CHANS + PADC + i] = 0.f; }
    float wv[SCOPE];
#pragma unroll
    for (int k = 0; k < SCOPE; ++k) wv[k] = w[k];
    float v = (i == j) ? 1.f : 0.f;
    for (int s = 0; s < STEPS; ++s){
        __syncthreads();
        sv[PADC + i] = v;
        __syncthreads();
        float acc = (i == j) ? 1.f : 0.f;
#pragma unroll
        for (int k = 0; k < SCOPE; ++k) acc = fmaf(wv[k], sv[i + k], acc);
        v = acc;
    }
    g_wh[j * CHANS + i] = __float2half_rn(v);
}

// ---------------- Kernel 2: out = W_eff * X via fp16 mma.sync ----------------
// Both operands in SMEM as k-paired fp16 u32 {v(2k), v(2k+1)} at [k2][col]:
// every mma fragment register = one LDS.32. X staged via LDG.128 -> cvt -> STS.128
// (2-deep manual pipeline); W staged LDG+PRMT (L2-hot). One barrier per chunk.
__global__ void __launch_bounds__(256, 2)
gemm_kernel(const float* __restrict__ x, float* __restrict__ out){
    extern __shared__ uint32_t smu[];
    uint32_t* xbuf = smu;              // 2 x [16][XSTR]
    uint32_t* wbuf = smu + 2*XBUF;     // 2 x [16][WSTR]

    const int tid  = threadIdx.x;
    const int lane = tid & 31;
    const int wid  = tid >> 5;
    const int g = lane >> 2, q = lane & 3;
    const int wp = wid >> 1, wc = wid & 1;
    const int chalf = blockIdx.x;      // 0..1 (adjacent bids share X in L2)
    const int tile  = blockIdx.y;      // 0..783

    // staging coords: thread -> (k2 row, 8 consecutive pos)
    const int sk2 = tid >> 4;              // 0..15
    const int sp0 = (tid & 15) << 3;       // 0,8,...,120
    const int sn  = tile * TILE_P + sp0;   // 8|3136 -> segment never straddles b
    const int sb  = sn / HWSZ;
    const int spp = sn - sb * HWSZ;
    const float* xsrc = x + ((size_t)sb * CHANS + 2 * sk2) * HWSZ + spp;

    float4 xf[4];
    auto ldg_x = [&](int kc){
        const float* s0 = xsrc + (size_t)(kc * KC) * HWSZ;
        const float* s1 = s0 + HWSZ;
        xf[0] = *(const float4*)s0;
        xf[1] = *(const float4*)(s0 + 4);
        xf[2] = *(const float4*)s1;
        xf[3] = *(const float4*)(s1 + 4);
    };
    auto sts_x = [&](uint32_t* buf){
        uint32_t* d = buf + sk2 * XSTR + sp0;
        uint4 v0, v1;
        v0.x = pkh2(xf[2].x, xf[0].x);  v0.y = pkh2(xf[2].y, xf[0].y);
        v0.z = pkh2(xf[2].z, xf[0].z);  v0.w = pkh2(xf[2].w, xf[0].w);
        v1.x = pkh2(xf[3].x, xf[1].x);  v1.y = pkh2(xf[3].y, xf[1].y);
        v1.z = pkh2(xf[3].z, xf[1].z);  v1.w = pkh2(xf[3].w, xf[1].w);
        *(uint4*)d       = v0;
        *(uint4*)(d + 4) = v1;
    };
    auto stage_w = [&](int kc, uint32_t* buf){
#pragma unroll
        for (int i = 0; i < 4; ++i){
            int id  = tid + i * 256;
            int k2l = id >> 6;
            int n2  = (id & 63) << 1;
            const __half* r0 = g_wh + (size_t)(kc * KC + 2 * k2l) * CHANS + chalf * TILE_C + n2;
            uint32_t a = *(const uint32_t*)r0;
            uint32_t b = *(const uint32_t*)(r0 + CHANS);
            *(uint2*)(buf + k2l * WSTR + n2) =
                make_uint2(prmt(a, b, 0x5410), prmt(a, b, 0x7632));
        }
    };

    float acc[2][8][4];
#pragma unroll
    for (int mt = 0; mt < 2; ++mt)
#pragma unroll
        for (int nt = 0; nt < 8; ++nt)
#pragma unroll
            for (int r = 0; r < 4; ++r) acc[mt][nt][r] = 0.f;

    // prologue: chunk0 into smem, chunk1 into regs
    ldg_x(0);
    stage_w(0, wbuf);
    sts_x(xbuf);
    stage_w(1, wbuf + WBUF);
    ldg_x(1);
    __syncthreads();

    for (int c = 0; c < NCHUNK; ++c){
        const uint32_t* xb = xbuf + (c & 1) * XBUF;
        const uint32_t* wb = wbuf + (c & 1) * WBUF;
#pragma unroll
        for (int ks = 0; ks < 2; ++ks){
            const uint32_t* xk = xb + (ks * 8 + q) * XSTR + wp * 32;
            uint32_t a[2][4];
#pragma unroll
            for (int mt = 0; mt < 2; ++mt){
                int p0 = mt * 16 + g;
                a[mt][0] = xk[p0];
                a[mt][1] = xk[p0 + 8];
                a[mt][2] = xk[4 * XSTR + p0];
                a[mt][3] = xk[4 * XSTR + p0 + 8];
            }
            const uint32_t* wk = wb + (ks * 8 + q) * WSTR + wc * 64 + g;
#pragma unroll
            for (int nt = 0; nt < 8; ++nt){
                uint32_t b0 = wk[nt * 8];
                uint32_t b1 = wk[4 * WSTR + nt * 8];
                mma16(acc[0][nt], a[0], b0, b1);
                mma16(acc[1][nt], a[1], b0, b1);
            }
        }
        if (c < NCHUNK - 1){
            // safe single-sync: writers of buffer (c+1)&1 run only after the
            // end-of-(c-1) barrier, by which all warps finished reading chunk c-1.
            sts_x(xbuf + ((c + 1) & 1) * XBUF);
            stage_w(c + 1, wbuf + ((c + 1) & 1) * WBUF);
            if (c < NCHUNK - 2) ldg_x(c + 2);
            __syncthreads();
        }
    }

    // epilogue: frag rows g|g+8, cols 2q,2q+1 -> out[cout][b,p]
#pragma unroll
    for (int mt = 0; mt < 2; ++mt){
#pragma unroll
        for (int rs = 0; rs < 2; ++rs){
            int pos = tile * TILE_P + wp * 32 + mt * 16 + g + rs * 8;
            int b = pos / HWSZ, p = pos - b * HWSZ;
            float* ob = out + ((size_t)b * CHANS + (size_t)(chalf * TILE_C + wc * 64 + 2 * q)) * HWSZ + p;
#pragma unroll
            for (int nt = 0; nt < 8; ++nt){
                ob[(size_t)(nt * 8) * HWSZ]     = acc[mt][nt][rs * 2 + 0];
                ob[(size_t)(nt * 8 + 1) * HWSZ] = acc[mt][nt][rs * 2 + 1];
            }
        }
    }
}

// ---------------- launch ----------------
extern "C" void kernel_launch(void* const* d_in, const int* in_sizes, int n_in,
                              void* d_out, int out_size)
{
    const float* acts = (const float*)d_in[0];
    const float* wrec = (const float*)d_in[1];
    float* out        = (float*)d_out;
    (void)in_sizes; (void)n_in; (void)out_size;

    cudaFuncSetAttribute(gemm_kernel, cudaFuncAttributeMaxDynamicSharedMemorySize, SMEM_BYTES);

    build_weff_kernel<<<CHANS, CHANS>>>(wrec);
    gemm_kernel<<<dim3(2, NPOS / TILE_P), 256, SMEM_BYTES>>>(acts, out);
}